// round 1
// baseline (speedup 1.0000x reference)
#include <cuda_runtime.h>
#include <cuda_bf16.h>

#define NRAYS 4096
#define NTETS 3072
#define NFACE 12288
#define MAXS  128

// ---------------- scratch (device globals; no allocations allowed) ----------
__device__ float4 g_tri[NFACE * 3];              // per-tri: p0, e1, e2 (w unused)
__device__ unsigned long long g_key[NRAYS];      // packed (t_bits<<32 | tri_idx)

struct F3 { float x, y, z; };
__device__ __forceinline__ F3 mkf3(float x, float y, float z) { F3 r; r.x = x; r.y = y; r.z = z; return r; }
__device__ __forceinline__ F3 sub3(F3 a, F3 b) { return mkf3(a.x - b.x, a.y - b.y, a.z - b.z); }
__device__ __forceinline__ F3 cross3(F3 a, F3 b) {
    return mkf3(a.y * b.z - a.z * b.y,
                a.z * b.x - a.x * b.z,
                a.x * b.y - a.y * b.x);
}
__device__ __forceinline__ float dot3(F3 a, F3 b) { return a.x * b.x + a.y * b.y + a.z * b.z; }
__device__ __forceinline__ F3 ld3(const float* p) { return mkf3(p[0], p[1], p[2]); }

// ---------------- kernel 0: reset per-ray min keys --------------------------
__global__ void k_init_keys() {
    int i = blockIdx.x * blockDim.x + threadIdx.x;
    if (i < NRAYS)
        g_key[i] = ((unsigned long long)__float_as_uint(1e10f) << 32); // (1e10, idx 0)
}

// ---------------- kernel 1: precompute triangle (p0, e1, e2) ----------------
__global__ void k_prep(const float* __restrict__ verts, const int* __restrict__ faces) {
    int i = blockIdx.x * blockDim.x + threadIdx.x;
    if (i >= NFACE) return;
    int v0 = faces[3 * i + 0];
    int v1 = faces[3 * i + 1];
    int v2 = faces[3 * i + 2];
    F3 p0 = ld3(verts + 3 * v0);
    F3 p1 = ld3(verts + 3 * v1);
    F3 p2 = ld3(verts + 3 * v2);
    g_tri[3 * i + 0] = make_float4(p0.x, p0.y, p0.z, 0.0f);
    g_tri[3 * i + 1] = make_float4(p1.x - p0.x, p1.y - p0.y, p1.z - p0.z, 0.0f);
    g_tri[3 * i + 2] = make_float4(p2.x - p0.x, p2.y - p0.y, p2.z - p0.z, 0.0f);
}

// ---------------- kernel 2: Moller-Trumbore, (ray-group x tri-group) --------
// grid = (16, 12): blockIdx.x selects 256 rays, blockIdx.y selects 1024 tris.
// All threads in a block iterate the same triangle each step (L1 broadcast).
// Global atomicMin on packed (t, idx) reproduces first-occurrence argmin.
__global__ void __launch_bounds__(256) k_isect(const float* __restrict__ ro,
                                               const float* __restrict__ rd) {
    int ray = blockIdx.x * 256 + threadIdx.x;
    F3 o = ld3(ro + 3 * ray);
    F3 d = ld3(rd + 3 * ray);

    float tmin = 1e10f;
    int   fmin = 0;
    int   base = blockIdx.y * 1024;

#pragma unroll 2
    for (int t = 0; t < 1024; ++t) {
        int ti = base + t;
        float4 q0 = g_tri[3 * ti + 0];
        float4 q1 = g_tri[3 * ti + 1];
        float4 q2 = g_tri[3 * ti + 2];
        F3 p0 = mkf3(q0.x, q0.y, q0.z);
        F3 e1 = mkf3(q1.x, q1.y, q1.z);
        F3 e2 = mkf3(q2.x, q2.y, q2.z);

        F3 h = cross3(d, e2);
        float a = dot3(e1, h);
        bool anz = fabsf(a) > 1e-9f;
        float f = 1.0f / (anz ? a : 1e-9f);
        F3 s = sub3(o, p0);
        float u = f * dot3(s, h);
        F3 q = cross3(s, e1);
        float v = f * dot3(d, q);
        float tt = f * dot3(e2, q);
        bool ok = anz && (u >= 0.0f) && (u <= 1.0f) && (v >= 0.0f) &&
                  (u + v <= 1.0f) && (tt > 1e-6f);
        if (ok && tt < tmin) { tmin = tt; fmin = ti; }
    }

    unsigned long long key =
        ((unsigned long long)__float_as_uint(tmin) << 32) | (unsigned)fmin;
    atomicMin(&g_key[ray], key);
}

// ---------------- barycentric solve (Cramer) ---------------------------------
__device__ __forceinline__ void bary4(const float* __restrict__ verts,
                                      const int* __restrict__ tetras,
                                      int tet, F3 p,
                                      float& w0, float& w1, float& w2, float& w3) {
    int4 tv = ((const int4*)tetras)[tet];
    F3 a  = ld3(verts + 3 * tv.x);
    F3 b  = ld3(verts + 3 * tv.y);
    F3 c  = ld3(verts + 3 * tv.z);
    F3 dd = ld3(verts + 3 * tv.w);
    F3 e1 = sub3(b, a);
    F3 e2 = sub3(c, a);
    F3 e3 = sub3(dd, a);
    F3 r  = sub3(p, a);

    F3 c23 = cross3(e2, e3);
    float det = dot3(e1, c23);
    float inv = 1.0f / det;
    w1 = dot3(r, c23) * inv;
    F3 cr3 = cross3(r, e3);
    w2 = dot3(e1, cr3) * inv;
    F3 c2r = cross3(e2, r);
    w3 = dot3(e1, c2r) * inv;
    w0 = 1.0f - (w1 + w2 + w3);
}

// ---------------- kernel 3: per-ray march with tet walk ---------------------
__global__ void k_march(const float* __restrict__ verts,
                        const float* __restrict__ ro,
                        const float* __restrict__ rd,
                        const int* __restrict__ tetras,
                        const int* __restrict__ topo,
                        float* __restrict__ out) {
    int ray = blockIdx.x * blockDim.x + threadIdx.x;
    if (ray >= NRAYS) return;

    unsigned long long key = g_key[ray];
    float tmin = __uint_as_float((unsigned)(key >> 32));
    int   fidx = (int)(key & 0xffffffffu);

    bool  hit = tmin < 5.0f;
    float t0  = hit ? tmin : 0.0f;
    F3 o = ld3(ro + 3 * ray);
    F3 d = ld3(rd + 3 * ray);
    F3 hp = mkf3(o.x + t0 * d.x, o.y + t0 * d.y, o.z + t0 * d.z);
    int  tet   = hit ? (fidx >> 2) : 0;
    bool alive = hit;

    float* o_ray = out;
    float* o_tet = out + (size_t)NRAYS * MAXS;
    float* o_bar = out + (size_t)2 * NRAYS * MAXS;
    float* o_ts  = out + (size_t)6 * NRAYS * MAXS;
    float* o_te  = o_ts + NRAYS;
    float* o_pos = o_te + NRAYS;

    o_ts[ray] = t0;
    o_te[ray] = hit ? (t0 + 0.05f) : 0.0f;

    const float STEPF = (float)(0.05 / 128.0);

    for (int k = 0; k < MAXS; ++k) {
        int idx = ray * MAXS + k;
        float w0 = 0.f, w1 = 0.f, w2 = 0.f, w3 = 0.f;
        F3 p = mkf3(0.f, 0.f, 0.f);
        bool valid = false;

        if (alive) {
            float tk = (float)k * STEPF + 1e-4f;
            p = mkf3(hp.x + tk * d.x, hp.y + tk * d.y, hp.z + tk * d.z);

            bool inside = false;
            int  wt = -1;
            for (int it = 0; it < 3; ++it) {
                bary4(verts, tetras, tet, p, w0, w1, w2, w3);
                wt = tet;
                inside = (w0 >= -1e-6f) && (w1 >= -1e-6f) &&
                         (w2 >= -1e-6f) && (w3 >= -1e-6f);
                if (inside) break;
                // first-occurrence argmin over (w0,w1,w2,w3)
                int am = 0; float mv = w0;
                if (w1 < mv) { mv = w1; am = 1; }
                if (w2 < mv) { mv = w2; am = 2; }
                if (w3 < mv) { mv = w3; am = 3; }
                int nb = topo[4 * tet + (3 - am)];
                if (nb >= 0) tet = nb;
                else { alive = false; break; }
            }
            if (alive && wt != tet) {
                bary4(verts, tetras, tet, p, w0, w1, w2, w3);
                inside = (w0 >= -1e-6f) && (w1 >= -1e-6f) &&
                         (w2 >= -1e-6f) && (w3 >= -1e-6f);
            }
            valid = alive && inside;
        }

        if (valid) {
            o_ray[idx] = (float)ray;
            o_tet[idx] = (float)tet;
            o_bar[4 * idx + 0] = w0;
            o_bar[4 * idx + 1] = w1;
            o_bar[4 * idx + 2] = w2;
            o_bar[4 * idx + 3] = w3;
            o_pos[3 * idx + 0] = p.x;
            o_pos[3 * idx + 1] = p.y;
            o_pos[3 * idx + 2] = p.z;
        } else {
            o_ray[idx] = -1.0f;
            o_tet[idx] = -1.0f;
            o_bar[4 * idx + 0] = 0.0f;
            o_bar[4 * idx + 1] = 0.0f;
            o_bar[4 * idx + 2] = 0.0f;
            o_bar[4 * idx + 3] = 0.0f;
            o_pos[3 * idx + 0] = 0.0f;
            o_pos[3 * idx + 1] = 0.0f;
            o_pos[3 * idx + 2] = 0.0f;
        }
    }
}

// ---------------- launch ------------------------------------------------------
extern "C" void kernel_launch(void* const* d_in, const int* in_sizes, int n_in,
                              void* d_out, int out_size) {
    const float* cage   = (const float*)d_in[0];  // (1, 729, 3) f32
    const float* ro     = (const float*)d_in[1];  // (1, 4096, 3) f32
    const float* rd     = (const float*)d_in[2];  // (1, 4096, 3) f32
    const int*   tetras = (const int*)d_in[3];    // (3072, 4) i32
    const int*   faces  = (const int*)d_in[4];    // (3072, 4, 3) i32
    const int*   topo   = (const int*)d_in[5];    // (3072, 4) i32
    float* out = (float*)d_out;

    k_init_keys<<<(NRAYS + 255) / 256, 256>>>();
    k_prep<<<(NFACE + 255) / 256, 256>>>(cage, faces);
    dim3 g(NRAYS / 256, NFACE / 1024);  // (16, 12)
    k_isect<<<g, 256>>>(ro, rd);
    k_march<<<(NRAYS + 127) / 128, 128>>>(cage, ro, rd, tetras, topo, out);
}

// round 3
// speedup vs baseline: 5.5822x; 5.5822x over previous
#include <cuda_runtime.h>
#include <cuda_bf16.h>

#define NRAYS 4096
#define NTETS 3072
#define NFACE 12288
#define MAXS  128

// ---------------- scratch (device globals; no allocations) ------------------
__device__ float4 g_btri[NFACE * 3];            // boundary tri: p0,e1,e2; fid in [0].w
__device__ int    g_nb;                          // boundary tri count
__device__ unsigned long long g_key[NRAYS];      // packed (t_bits<<32 | face_idx)

struct F3 { float x, y, z; };
__device__ __forceinline__ F3 mkf3(float x, float y, float z) { F3 r; r.x = x; r.y = y; r.z = z; return r; }
__device__ __forceinline__ F3 sub3(F3 a, F3 b) { return mkf3(a.x - b.x, a.y - b.y, a.z - b.z); }
__device__ __forceinline__ F3 cross3(F3 a, F3 b) {
    return mkf3(a.y * b.z - a.z * b.y,
                a.z * b.x - a.x * b.z,
                a.x * b.y - a.y * b.x);
}
__device__ __forceinline__ float dot3(F3 a, F3 b) { return a.x * b.x + a.y * b.y + a.z * b.z; }
__device__ __forceinline__ F3 ld3(const float* p) { return mkf3(p[0], p[1], p[2]); }

// ---------------- kernel 0: reset keys + counter ----------------------------
__global__ void k_init() {
    int i = blockIdx.x * blockDim.x + threadIdx.x;
    if (i < NRAYS)
        g_key[i] = ((unsigned long long)__float_as_uint(1e10f) << 32); // (1e10, idx 0)
    if (i == 0) g_nb = 0;
}

// ---------------- kernel 1: compact boundary triangles ----------------------
// topo is (NTETS,4) flattened => topo[fid] corresponds exactly to face fid.
// First hit of a ray from outside a watertight mesh is always a boundary face.
__global__ void k_prep_faces(const float* __restrict__ verts,
                             const int* __restrict__ faces,
                             const int* __restrict__ topo) {
    int fid = blockIdx.x * blockDim.x + threadIdx.x;
    if (fid >= NFACE) return;
    if (topo[fid] >= 0) return;                 // interior face: cannot be first hit
    int slot = atomicAdd(&g_nb, 1);
    int v0 = faces[3 * fid + 0];
    int v1 = faces[3 * fid + 1];
    int v2 = faces[3 * fid + 2];
    F3 p0 = ld3(verts + 3 * v0);
    F3 p1 = ld3(verts + 3 * v1);
    F3 p2 = ld3(verts + 3 * v2);
    g_btri[3 * slot + 0] = make_float4(p0.x, p0.y, p0.z, __int_as_float(fid));
    g_btri[3 * slot + 1] = make_float4(p1.x - p0.x, p1.y - p0.y, p1.z - p0.z, 0.0f);
    g_btri[3 * slot + 2] = make_float4(p2.x - p0.x, p2.y - p0.y, p2.z - p0.z, 0.0f);
}

// ---------------- kernel 2: Moller-Trumbore over boundary tris ---------------
// grid (16, 8): blockIdx.x selects 256 rays; blockIdx.y strides the candidate
// list. atomicMin on packed (t, face_idx) reproduces first-occurrence argmin.
__global__ void __launch_bounds__(256) k_isect(const float* __restrict__ ro,
                                               const float* __restrict__ rd) {
    int ray = blockIdx.x * 256 + threadIdx.x;
    F3 o = ld3(ro + 3 * ray);
    F3 d = ld3(rd + 3 * ray);
    int nb = g_nb;

    float tmin = 1e10f;
    int   fmin = 0x7fffffff;

    for (int s = blockIdx.y; s < nb; s += 8) {
        float4 q0 = g_btri[3 * s + 0];
        float4 q1 = g_btri[3 * s + 1];
        float4 q2 = g_btri[3 * s + 2];
        F3 p0 = mkf3(q0.x, q0.y, q0.z);
        F3 e1 = mkf3(q1.x, q1.y, q1.z);
        F3 e2 = mkf3(q2.x, q2.y, q2.z);
        int fid = __float_as_int(q0.w);

        F3 h = cross3(d, e2);
        float a = dot3(e1, h);
        bool anz = fabsf(a) > 1e-9f;
        float f = 1.0f / (anz ? a : 1e-9f);
        F3 s3 = sub3(o, p0);
        float u = f * dot3(s3, h);
        F3 q = cross3(s3, e1);
        float v = f * dot3(d, q);
        float tt = f * dot3(e2, q);
        bool ok = anz && (u >= 0.0f) && (u <= 1.0f) && (v >= 0.0f) &&
                  (u + v <= 1.0f) && (tt > 1e-6f);
        if (ok && (tt < tmin || (tt == tmin && fid < fmin))) { tmin = tt; fmin = fid; }
    }

    if (tmin < 1e10f) {
        unsigned long long key =
            ((unsigned long long)__float_as_uint(tmin) << 32) | (unsigned)fmin;
        atomicMin(&g_key[ray], key);
    }
}

// ---------------- kernel 3: per-ray march, register-cached tet ---------------
// Bary arithmetic is IDENTICAL to the round-1 passing kernel (fresh Cramer:
// c23 = cross(e2,e3), det = dot(e1,c23), inv = 1/det, w_i via cross/dot/ *inv).
// c23/inv are pure functions of the tet's vertex data, so hoisting them into
// registers across steps is bit-identical while removing nearly all loads.
__global__ void __launch_bounds__(32) k_march(const float* __restrict__ verts,
                                              const float* __restrict__ ro,
                                              const float* __restrict__ rd,
                                              const int* __restrict__ tetras,
                                              const int* __restrict__ topo,
                                              float* __restrict__ out) {
    int ray = blockIdx.x * 32 + threadIdx.x;

    unsigned long long key = g_key[ray];
    float tmin = __uint_as_float((unsigned)(key >> 32));
    int   fidx = (int)(key & 0xffffffffu);

    bool  hit = tmin < 5.0f;
    float t0  = hit ? tmin : 0.0f;
    F3 o = ld3(ro + 3 * ray);
    F3 d = ld3(rd + 3 * ray);
    F3 hp = mkf3(o.x + t0 * d.x, o.y + t0 * d.y, o.z + t0 * d.z);
    int  tet   = hit ? (fidx >> 2) : 0;
    bool alive = hit;

    float* o_ray = out;
    float* o_tet = out + (size_t)NRAYS * MAXS;
    float* o_bar = out + (size_t)2 * NRAYS * MAXS;
    float* o_ts  = out + (size_t)6 * NRAYS * MAXS;
    float* o_te  = o_ts + NRAYS;
    float* o_pos = o_te + NRAYS;

    o_ts[ray] = t0;
    o_te[ray] = hit ? (t0 + 0.05f) : 0.0f;

    const float STEPF = (float)(0.05 / 128.0);

    // register-cached tet data (identical computation to R1's bary4 preamble)
    F3 ca, ce1, ce2, ce3, cc23;
    float cinv = 0.0f;
    if (alive) {
        int4 tv = ((const int4*)tetras)[tet];
        ca  = ld3(verts + 3 * tv.x);
        F3 b  = ld3(verts + 3 * tv.y);
        F3 c  = ld3(verts + 3 * tv.z);
        F3 dd = ld3(verts + 3 * tv.w);
        ce1 = sub3(b, ca);
        ce2 = sub3(c, ca);
        ce3 = sub3(dd, ca);
        cc23 = cross3(ce2, ce3);
        float det = dot3(ce1, cc23);
        cinv = 1.0f / det;
    }

    for (int k = 0; k < MAXS; ++k) {
        int idx = ray * MAXS + k;
        float w0 = 0.f, w1 = 0.f, w2 = 0.f, w3 = 0.f;
        F3 p = mkf3(0.f, 0.f, 0.f);
        bool valid = false;

        if (alive) {
            float tk = (float)k * STEPF + 1e-4f;
            p = mkf3(hp.x + tk * d.x, hp.y + tk * d.y, hp.z + tk * d.z);

            bool inside = false;
            bool moved_last = false;
            for (int it = 0; it < 3; ++it) {
                F3 r = sub3(p, ca);
                w1 = dot3(r, cc23) * cinv;
                F3 cr3 = cross3(r, ce3);
                w2 = dot3(ce1, cr3) * cinv;
                F3 c2r = cross3(ce2, r);
                w3 = dot3(ce1, c2r) * cinv;
                w0 = 1.0f - (w1 + w2 + w3);
                inside = (w0 >= -1e-6f) && (w1 >= -1e-6f) &&
                         (w2 >= -1e-6f) && (w3 >= -1e-6f);
                moved_last = false;
                if (inside) break;
                int am = 0; float mv = w0;
                if (w1 < mv) { mv = w1; am = 1; }
                if (w2 < mv) { mv = w2; am = 2; }
                if (w3 < mv) { mv = w3; am = 3; }
                int nb = topo[4 * tet + (3 - am)];
                if (nb >= 0) {
                    tet = nb;
                    int4 tv = ((const int4*)tetras)[tet];
                    ca  = ld3(verts + 3 * tv.x);
                    F3 b  = ld3(verts + 3 * tv.y);
                    F3 c  = ld3(verts + 3 * tv.z);
                    F3 dd = ld3(verts + 3 * tv.w);
                    ce1 = sub3(b, ca);
                    ce2 = sub3(c, ca);
                    ce3 = sub3(dd, ca);
                    cc23 = cross3(ce2, ce3);
                    float det = dot3(ce1, cc23);
                    cinv = 1.0f / det;
                    moved_last = true;
                } else { alive = false; break; }
            }
            if (alive && !inside && moved_last) {
                F3 r = sub3(p, ca);
                w1 = dot3(r, cc23) * cinv;
                F3 cr3 = cross3(r, ce3);
                w2 = dot3(ce1, cr3) * cinv;
                F3 c2r = cross3(ce2, r);
                w3 = dot3(ce1, c2r) * cinv;
                w0 = 1.0f - (w1 + w2 + w3);
                inside = (w0 >= -1e-6f) && (w1 >= -1e-6f) &&
                         (w2 >= -1e-6f) && (w3 >= -1e-6f);
            }
            valid = alive && inside;
        }

        if (valid) {
            o_ray[idx] = (float)ray;
            o_tet[idx] = (float)tet;
            ((float4*)o_bar)[idx] = make_float4(w0, w1, w2, w3);
            o_pos[3 * idx + 0] = p.x;
            o_pos[3 * idx + 1] = p.y;
            o_pos[3 * idx + 2] = p.z;
        } else {
            o_ray[idx] = -1.0f;
            o_tet[idx] = -1.0f;
            ((float4*)o_bar)[idx] = make_float4(0.f, 0.f, 0.f, 0.f);
            o_pos[3 * idx + 0] = 0.0f;
            o_pos[3 * idx + 1] = 0.0f;
            o_pos[3 * idx + 2] = 0.0f;
        }
    }
}

// ---------------- launch ------------------------------------------------------
extern "C" void kernel_launch(void* const* d_in, const int* in_sizes, int n_in,
                              void* d_out, int out_size) {
    const float* cage   = (const float*)d_in[0];  // (1, 729, 3) f32
    const float* ro     = (const float*)d_in[1];  // (1, 4096, 3) f32
    const float* rd     = (const float*)d_in[2];  // (1, 4096, 3) f32
    const int*   tetras = (const int*)d_in[3];    // (3072, 4) i32
    const int*   faces  = (const int*)d_in[4];    // (3072, 4, 3) i32
    const int*   topo   = (const int*)d_in[5];    // (3072, 4) i32
    float* out = (float*)d_out;

    k_init<<<(NRAYS + 255) / 256, 256>>>();
    k_prep_faces<<<(NFACE + 255) / 256, 256>>>(cage, faces, topo);
    dim3 g(NRAYS / 256, 8);  // (16, 8)
    k_isect<<<g, 256>>>(ro, rd);
    k_march<<<NRAYS / 32, 32>>>(cage, ro, rd, tetras, topo, out);
}